// round 6
// baseline (speedup 1.0000x reference)
#include <cuda_runtime.h>
#include <math.h>
#include <stdint.h>

// ---------------- problem constants ----------------
#define BB 4
#define TT 1024
#define EE 768
#define HH 12
#define HD 64
#define LL 4
#define VV 50257
#define MM (BB*TT)          // 4096 rows
#define E3 (3*EE)           // 2304
#define E4 (4*EE)           // 3072
#define LN_EPS 1e-5f
#define L2E 1.4426950408889634f

// ---------------- scratch (static device allocations; no cudaMalloc) ----------------
__device__ __align__(256) float g_x   [(size_t)MM*EE];
__device__ __align__(256) float g_xn  [(size_t)MM*EE];
__device__ __align__(256) float g_qkv [(size_t)MM*E3];
__device__ __align__(256) float g_y   [(size_t)MM*EE];
__device__ __align__(256) float g_h1  [(size_t)MM*E4];
__device__ __align__(256) float g_nll [MM];
__device__ __align__(256) float g_logits_fb[(size_t)MM*VV];   // fallback logits store

// ---------------- embedding ----------------
__global__ void embed_kernel(const int* __restrict__ idx,
                             const float* __restrict__ wte,
                             const float* __restrict__ wpe,
                             float* __restrict__ X)
{
    int i = blockIdx.x * 256 + threadIdx.x;
    if (i >= MM * EE) return;
    int m = i / EE;
    int e = i - m * EE;
    int tok = idx[m];
    X[i] = wte[(size_t)tok * EE + e] + wpe[(size_t)(m & (TT - 1)) * EE + e];
}

// ---------------- layernorm (one block per row, 256 threads, E=768) ----------------
__global__ void ln_kernel(const float* __restrict__ X,
                          const float* __restrict__ w,
                          const float* __restrict__ b,
                          float* __restrict__ O)
{
    int row = blockIdx.x;
    int t   = threadIdx.x;
    const float* xr = X + (size_t)row * EE;
    float v0 = xr[t], v1 = xr[t + 256], v2 = xr[t + 512];
    float s  = v0 + v1 + v2;
    float ss = v0 * v0 + v1 * v1 + v2 * v2;
    #pragma unroll
    for (int o = 16; o > 0; o >>= 1) {
        s  += __shfl_xor_sync(0xffffffffu, s, o);
        ss += __shfl_xor_sync(0xffffffffu, ss, o);
    }
    __shared__ float rs[8], rss[8];
    int wid = t >> 5, lid = t & 31;
    if (lid == 0) { rs[wid] = s; rss[wid] = ss; }
    __syncthreads();
    s = 0.f; ss = 0.f;
    #pragma unroll
    for (int i = 0; i < 8; i++) { s += rs[i]; ss += rss[i]; }
    float mean = s * (1.0f / EE);
    float var  = ss * (1.0f / EE) - mean * mean;
    float inv  = rsqrtf(var + LN_EPS);
    float* orow = O + (size_t)row * EE;
    orow[t]       = (v0 - mean) * inv * w[t]       + b[t];
    orow[t + 256] = (v1 - mean) * inv * w[t + 256] + b[t + 256];
    orow[t + 512] = (v2 - mean) * inv * w[t + 512] + b[t + 512];
}

// ---------------- SGEMM: C[M,N] = A[M,K] @ W[N,K]^T (+bias)(+res)(+gelu) ----------------
// epi: 0 = plain(+bias if bias!=null), 2 = +residual, 3 = +gelu
// Vectorized epilogue only when N % 4 == 0 (odd N, e.g. V=50257, makes row
// bases 4B-aligned only — float4 stores there were the R4 crash).
__global__ __launch_bounds__(256, 2)
void sgemm_nt(const float* __restrict__ A, const float* __restrict__ W,
              const float* __restrict__ bias, const float* __restrict__ res,
              float* __restrict__ C, int M, int N, int K, int epi)
{
    __shared__ __align__(16) float As[2][8][132];
    __shared__ __align__(16) float Bs[2][8][132];

    const int t  = threadIdx.x;
    const int bm = blockIdx.y * 128;
    const int bn = blockIdx.x * 128;
    const int lr = t >> 1;
    const int lc = (t & 1) * 4;
    const int tx = t & 15;
    const int ty = t >> 4;

    const float* Aptr = A + (size_t)(bm + lr) * K + lc;
    const int    wrow = bn + lr;
    const float* Wptr = W + (size_t)wrow * K + lc;
    const bool   wok  = (wrow < N);

    float4 ra = *(const float4*)Aptr;
    float4 rb = wok ? *(const float4*)Wptr : make_float4(0.f, 0.f, 0.f, 0.f);

    float c[8][8];
    #pragma unroll
    for (int i = 0; i < 8; i++)
        #pragma unroll
        for (int j = 0; j < 8; j++) c[i][j] = 0.f;

    int buf = 0;
    As[0][lc + 0][lr] = ra.x; As[0][lc + 1][lr] = ra.y;
    As[0][lc + 2][lr] = ra.z; As[0][lc + 3][lr] = ra.w;
    Bs[0][lc + 0][lr] = rb.x; Bs[0][lc + 1][lr] = rb.y;
    Bs[0][lc + 2][lr] = rb.z; Bs[0][lc + 3][lr] = rb.w;
    __syncthreads();

    for (int kk = 0; kk < K; kk += 8) {
        bool more = (kk + 8) < K;
        if (more) {
            ra = *(const float4*)(Aptr + kk + 8);
            rb = wok ? *(const float4*)(Wptr + kk + 8) : make_float4(0.f, 0.f, 0.f, 0.f);
        }
        #pragma unroll
        for (int k = 0; k < 8; k++) {
            float4 a0 = *(const float4*)&As[buf][k][ty * 4];
            float4 a1 = *(const float4*)&As[buf][k][64 + ty * 4];
            float4 b0 = *(const float4*)&Bs[buf][k][tx * 4];
            float4 b1 = *(const float4*)&Bs[buf][k][64 + tx * 4];
            float a[8] = {a0.x, a0.y, a0.z, a0.w, a1.x, a1.y, a1.z, a1.w};
            float b[8] = {b0.x, b0.y, b0.z, b0.w, b1.x, b1.y, b1.z, b1.w};
            #pragma unroll
            for (int i = 0; i < 8; i++)
                #pragma unroll
                for (int j = 0; j < 8; j++)
                    c[i][j] += a[i] * b[j];
        }
        if (more) {
            int nb = buf ^ 1;
            As[nb][lc + 0][lr] = ra.x; As[nb][lc + 1][lr] = ra.y;
            As[nb][lc + 2][lr] = ra.z; As[nb][lc + 3][lr] = ra.w;
            Bs[nb][lc + 0][lr] = rb.x; Bs[nb][lc + 1][lr] = rb.y;
            Bs[nb][lc + 2][lr] = rb.z; Bs[nb][lc + 3][lr] = rb.w;
            __syncthreads();
            buf = nb;
        }
    }

    const bool vec_ok = ((N & 3) == 0);

    #pragma unroll
    for (int gi = 0; gi < 2; gi++) {
        #pragma unroll
        for (int i = 0; i < 4; i++) {
            int row = bm + gi * 64 + ty * 4 + i;
            float* Crow = C + (size_t)row * N;
            const float* Rrow = res + (size_t)row * N;  // only deref if epi==2
            #pragma unroll
            for (int gj = 0; gj < 2; gj++) {
                int col = bn + gj * 64 + tx * 4;
                float v[4] = {c[gi * 4 + i][gj * 4 + 0], c[gi * 4 + i][gj * 4 + 1],
                              c[gi * 4 + i][gj * 4 + 2], c[gi * 4 + i][gj * 4 + 3]};
                if (vec_ok && col + 3 < N) {
                    if (bias) {
                        float4 bb = *(const float4*)(bias + col);
                        v[0] += bb.x; v[1] += bb.y; v[2] += bb.z; v[3] += bb.w;
                    }
                    if (epi == 2) {
                        float4 rr = *(const float4*)(Rrow + col);
                        v[0] += rr.x; v[1] += rr.y; v[2] += rr.z; v[3] += rr.w;
                    } else if (epi == 3) {
                        #pragma unroll
                        for (int u = 0; u < 4; u++)
                            v[u] = 0.5f * v[u] * (1.0f + erff(v[u] * 0.70710678118654752f));
                    }
                    *(float4*)(Crow + col) = make_float4(v[0], v[1], v[2], v[3]);
                } else {
                    #pragma unroll
                    for (int u = 0; u < 4; u++) {
                        if (col + u < N) {
                            float vv = v[u];
                            if (bias) vv += bias[col + u];
                            if (epi == 2) vv += Rrow[col + u];
                            else if (epi == 3) vv = 0.5f * vv * (1.0f + erff(vv * 0.70710678118654752f));
                            Crow[col + u] = vv;
                        }
                    }
                }
            }
        }
    }
}

// ---------------- causal attention (flash-style, 1 thread = 1 query row) -----------
__global__ __launch_bounds__(128)
void attn_kernel(const float* __restrict__ qkv, float* __restrict__ Y)
{
    int qt = blockIdx.x, h = blockIdx.y, b = blockIdx.z;
    int tid = threadIdx.x;
    int qi  = qt * 128 + tid;

    const float* base = qkv + (size_t)b * TT * E3;
    const float* qp   = base + (size_t)qi * E3 + h * HD;

    float q[HD], acc[HD];
    #pragma unroll
    for (int d = 0; d < HD; d += 4) {
        float4 u = *(const float4*)(qp + d);
        q[d] = u.x; q[d+1] = u.y; q[d+2] = u.z; q[d+3] = u.w;
        acc[d] = acc[d+1] = acc[d+2] = acc[d+3] = 0.f;
    }
    float mx = -INFINITY, l = 0.f;

    __shared__ __align__(16) float Ks[32][HD];
    __shared__ __align__(16) float Vs[32][HD];

    const float* kbase = base + EE     + h * HD;
    const float* vbase = base + 2 * EE + h * HD;
    int nkt = (qt + 1) * 4;   // tiles of 32 keys covering [0, qt*128+128)

    for (int kt = 0; kt < nkt; kt++) {
        int j0 = kt * 32;
        __syncthreads();
        #pragma unroll
        for (int w = 0; w < 4; w++) {
            int p4 = tid + w * 128;       // float4 index, 0..511
            int j  = p4 >> 4;
            int dc = (p4 & 15) * 4;
            *(float4*)&Ks[j][dc] = *(const float4*)(kbase + (size_t)(j0 + j) * E3 + dc);
            *(float4*)&Vs[j][dc] = *(const float4*)(vbase + (size_t)(j0 + j) * E3 + dc);
        }
        __syncthreads();

        #pragma unroll
        for (int half = 0; half < 2; half++) {
            int jb = half * 16;
            float s[16];
            #pragma unroll
            for (int j = 0; j < 16; j++) {
                float sum = 0.f;
                #pragma unroll
                for (int d = 0; d < HD; d += 4) {
                    float4 kv = *(const float4*)&Ks[jb + j][d];
                    sum += q[d] * kv.x + q[d+1] * kv.y + q[d+2] * kv.z + q[d+3] * kv.w;
                }
                s[j] = (j0 + jb + j <= qi) ? sum * 0.125f : -INFINITY;
            }
            float tmax = s[0];
            #pragma unroll
            for (int j = 1; j < 16; j++) tmax = fmaxf(tmax, s[j]);
            float nm   = fmaxf(mx, tmax);
            float corr = exp2f((mx - nm) * L2E);
            l *= corr;
            #pragma unroll
            for (int d = 0; d < HD; d++) acc[d] *= corr;
            #pragma unroll
            for (int j = 0; j < 16; j++) {
                float p = exp2f((s[j] - nm) * L2E);
                l += p;
                #pragma unroll
                for (int d = 0; d < HD; d += 4) {
                    float4 vv = *(const float4*)&Vs[jb + j][d];
                    acc[d]   += p * vv.x; acc[d+1] += p * vv.y;
                    acc[d+2] += p * vv.z; acc[d+3] += p * vv.w;
                }
            }
            mx = nm;
        }
    }
    float inv = 1.0f / l;
    float* yp = Y + (size_t)(b * TT + qi) * EE + h * HD;
    #pragma unroll
    for (int d = 0; d < HD; d += 4)
        *(float4*)(yp + d) = make_float4(acc[d] * inv, acc[d+1] * inv,
                                         acc[d+2] * inv, acc[d+3] * inv);
}

// ---------------- loss: per-row online logsumexp ----------------
__global__ void loss_row_kernel(const float* __restrict__ logits,
                                const int* __restrict__ tgt,
                                float* __restrict__ nll)
{
    int row = blockIdx.x;
    int t   = threadIdx.x;
    const float* Lr = logits + (size_t)row * VV;
    float mx = -INFINITY, s = 0.f;
    for (int j = t; j < VV; j += 256) {
        float x  = Lr[j];
        float nm = fmaxf(mx, x);
        s = s * exp2f((mx - nm) * L2E) + exp2f((x - nm) * L2E);
        mx = nm;
    }
    #pragma unroll
    for (int o = 16; o > 0; o >>= 1) {
        float om = __shfl_xor_sync(0xffffffffu, mx, o);
        float os = __shfl_xor_sync(0xffffffffu, s, o);
        float nm = fmaxf(mx, om);
        s = s * exp2f((mx - nm) * L2E) + os * exp2f((om - nm) * L2E);
        mx = nm;
    }
    __shared__ float sm[8], ssum[8];
    int wid = t >> 5, lid = t & 31;
    if (lid == 0) { sm[wid] = mx; ssum[wid] = s; }
    __syncthreads();
    if (t == 0) {
        float M = sm[0], S = ssum[0];
        #pragma unroll
        for (int i = 1; i < 8; i++) {
            float nm = fmaxf(M, sm[i]);
            S = S * exp2f((M - nm) * L2E) + ssum[i] * exp2f((sm[i] - nm) * L2E);
            M = nm;
        }
        int tg = tgt[row];
        nll[row] = (tg != -1) ? (M + logf(S)) - Lr[tg] : 0.f;
    }
}

__global__ void loss_final_kernel(const float* __restrict__ nll,
                                  const int* __restrict__ tgt,
                                  float* __restrict__ out)
{
    int t = threadIdx.x;
    float s = 0.f; int c = 0;
    for (int i = t; i < MM; i += 256) {
        if (tgt[i] != -1) { s += nll[i]; c++; }
    }
    #pragma unroll
    for (int o = 16; o > 0; o >>= 1) {
        s += __shfl_xor_sync(0xffffffffu, s, o);
        c += __shfl_xor_sync(0xffffffffu, c, o);
    }
    __shared__ float rs[8]; __shared__ int rc[8];
    int wid = t >> 5, lid = t & 31;
    if (lid == 0) { rs[wid] = s; rc[wid] = c; }
    __syncthreads();
    if (t == 0) {
        float S = 0.f; int C = 0;
        #pragma unroll
        for (int i = 0; i < 8; i++) { S += rs[i]; C += rc[i]; }
        out[0] = S / fmaxf((float)C, 1.f);
    }
}

// ---------------- launcher ----------------
extern "C" void kernel_launch(void* const* d_in, const int* in_sizes, int n_in,
                              void* d_out, int out_size)
{
    const int*   idx        = (const int*)  d_in[0];
    const int*   tgt        = (const int*)  d_in[1];
    const float* wte        = (const float*)d_in[2];
    const float* wpe        = (const float*)d_in[3];
    const float* ln1_w      = (const float*)d_in[4];
    const float* ln1_b      = (const float*)d_in[5];
    const float* attn_w     = (const float*)d_in[6];
    const float* attn_b     = (const float*)d_in[7];
    const float* attnproj_w = (const float*)d_in[8];
    const float* attnproj_b = (const float*)d_in[9];
    const float* ln2_w      = (const float*)d_in[10];
    const float* ln2_b      = (const float*)d_in[11];
    const float* fc_w       = (const float*)d_in[12];
    const float* fc_b       = (const float*)d_in[13];
    const float* proj_w     = (const float*)d_in[14];
    const float* proj_b     = (const float*)d_in[15];
    const float* lnf_w      = (const float*)d_in[16];
    const float* lnf_b      = (const float*)d_in[17];

    float *x, *xn, *qkv, *y, *h1, *nll, *lfb;
    cudaGetSymbolAddress((void**)&x,   g_x);
    cudaGetSymbolAddress((void**)&xn,  g_xn);
    cudaGetSymbolAddress((void**)&qkv, g_qkv);
    cudaGetSymbolAddress((void**)&y,   g_y);
    cudaGetSymbolAddress((void**)&h1,  g_h1);
    cudaGetSymbolAddress((void**)&nll, g_nll);
    cudaGetSymbolAddress((void**)&lfb, g_logits_fb);

    const long long BTV = (long long)MM * VV;
    float* logits = lfb;
    float* lossp  = nullptr;
    if ((long long)out_size == BTV + 1) { logits = (float*)d_out; lossp = (float*)d_out + BTV; }
    else if ((long long)out_size == BTV) { logits = (float*)d_out; }
    else { logits = lfb; lossp = (float*)d_out + (out_size - 1); }

    // embedding
    embed_kernel<<<(MM * EE + 255) / 256, 256>>>(idx, wte, wpe, x);

    for (int l = 0; l < LL; l++) {
        // --- attention block ---
        ln_kernel<<<MM, 256>>>(x, ln1_w + l * EE, ln1_b + l * EE, xn);
        sgemm_nt<<<dim3(E3 / 128, MM / 128), 256>>>(
            xn, attn_w + (size_t)l * E3 * EE, attn_b + (size_t)l * E3,
            nullptr, qkv, MM, E3, EE, 0);
        attn_kernel<<<dim3(TT / 128, HH, BB), 128>>>(qkv, y);
        sgemm_nt<<<dim3(EE / 128, MM / 128), 256>>>(
            y, attnproj_w + (size_t)l * EE * EE, attnproj_b + (size_t)l * EE,
            x, x, MM, EE, EE, 2);
        // --- mlp block ---
        ln_kernel<<<MM, 256>>>(x, ln2_w + l * EE, ln2_b + l * EE, xn);
        sgemm_nt<<<dim3(E4 / 128, MM / 128), 256>>>(
            xn, fc_w + (size_t)l * E4 * EE, fc_b + (size_t)l * E4,
            nullptr, h1, MM, E4, EE, 3);
        sgemm_nt<<<dim3(EE / 128, MM / 128), 256>>>(
            h1, proj_w + (size_t)l * EE * E4, proj_b + (size_t)l * EE,
            x, x, MM, EE, E4, 2);
    }

    // final LN + lm_head (tied wte)
    ln_kernel<<<MM, 256>>>(x, lnf_w, lnf_b, xn);
    sgemm_nt<<<dim3((VV + 127) / 128, MM / 128), 256>>>(
        xn, wte, nullptr, nullptr, logits, MM, VV, EE, 0);

    if (lossp) {
        loss_row_kernel<<<MM, 256>>>(logits, tgt, nll);
        loss_final_kernel<<<1, 256>>>(nll, tgt, lossp);
    }
}